// round 7
// baseline (speedup 1.0000x reference)
#include <cuda_runtime.h>
#include <cuda_bf16.h>

#define TILE 128
#define PAD  12
#define KWIN 9
#define DIL  3
#define HD   32
#define KV_W (TILE + 2*PAD)     /* 152 */
#define NQ4  (KV_W / 4)         /* 38 float4 groups per channel */
#define NSTG (HD * NQ4)         /* 1216 */

__device__ __forceinline__ void cp16(unsigned dst, const void* src) {
    asm volatile("cp.async.cg.shared.global [%0], [%1], 16;" :: "r"(dst), "l"(src));
}

__global__ __launch_bounds__(TILE, 8)
void dilated_attn_kernel(const float* __restrict__ q,
                         const float* __restrict__ k,
                         const float* __restrict__ v,
                         float* __restrict__ out)
{
    __shared__ float vs[HD][KV_W];   // V only: 19.5 KB -> 8 blocks/SM

    const int t    = threadIdx.x;
    const int tile = blockIdx.x & 31;          // L/TILE = 32
    const int h    = (blockIdx.x >> 5) & 15;   // 16 heads
    const int b    = blockIdx.x >> 9;          // 4 batches
    const int n0   = tile * TILE;
    const int n    = n0 + t;
    const int L    = 4096;
    const int d    = 512;

    const long cb = ((long)b * d + h * HD) * L;
    const float* qb = q + cb;
    const float* kb = k + cb;
    const float* vb = v + cb;

    const bool interior = (tile != 0) && (tile != 31);

    // ---- issue V staging first (async); latency hides behind QK ----
    if (interior) {
        const float* vsrc = vb + (n0 - PAD);
        #pragma unroll
        for (int it = 0; it < 10; it++) {
            const int idx = t + it * TILE;
            if (idx < NSTG) {
                const int c = idx / NQ4;
                const int g = idx - c * NQ4;
                const unsigned dst = (unsigned)__cvta_generic_to_shared(&vs[c][g * 4]);
                cp16(dst, vsrc + (long)c * L + g * 4);
            }
        }
    } else {
        #pragma unroll
        for (int it = 0; it < 10; it++) {
            const int idx = t + it * TILE;
            if (idx < NSTG) {
                const int c  = idx / NQ4;
                const int g  = idx - c * NQ4;
                const int ng = n0 - PAD + g * 4;
                float4 x;
                x.x = ((unsigned)(ng + 0) < (unsigned)L) ? vb[(long)c * L + ng + 0] : 0.f;
                x.y = ((unsigned)(ng + 1) < (unsigned)L) ? vb[(long)c * L + ng + 1] : 0.f;
                x.z = ((unsigned)(ng + 2) < (unsigned)L) ? vb[(long)c * L + ng + 2] : 0.f;
                x.w = ((unsigned)(ng + 3) < (unsigned)L) ? vb[(long)c * L + ng + 3] : 0.f;
                *(float4*)&vs[c][g * 4] = x;
            }
        }
    }
    asm volatile("cp.async.commit_group;");

    // ---- QK^T: k read directly from global (L1 reuse within each c-iter) ----
    float acc[KWIN];
    #pragma unroll
    for (int kk = 0; kk < KWIN; kk++) acc[kk] = 0.f;

    if (interior) {
        #pragma unroll 4
        for (int c = 0; c < HD; c++) {
            const float qc = qb[(long)c * L + n];
            const float* kc = kb + (long)c * L + (n - PAD);
            #pragma unroll
            for (int kk = 0; kk < KWIN; kk++)
                acc[kk] = fmaf(qc, kc[DIL * kk], acc[kk]);
        }
    } else {
        int   off[KWIN];
        float vld[KWIN];
        #pragma unroll
        for (int kk = 0; kk < KWIN; kk++) {
            const int tap = n - PAD + DIL * kk;
            vld[kk] = ((unsigned)tap < (unsigned)L) ? 1.f : 0.f;
            off[kk] = tap < 0 ? 0 : (tap >= L ? L - 1 : tap);
        }
        #pragma unroll 4
        for (int c = 0; c < HD; c++) {
            const float qc = qb[(long)c * L + n];
            const float* kc = kb + (long)c * L;
            #pragma unroll
            for (int kk = 0; kk < KWIN; kk++)
                acc[kk] = fmaf(qc, kc[off[kk]] * vld[kk], acc[kk]);
        }
    }

    // ---- softmax over 9 ----
    const float scale = 0.17677669529663687f;   // 32^-0.5
    float mx = -1e30f;
    #pragma unroll
    for (int kk = 0; kk < KWIN; kk++) { acc[kk] *= scale; mx = fmaxf(mx, acc[kk]); }
    float sum = 0.f;
    #pragma unroll
    for (int kk = 0; kk < KWIN; kk++) { acc[kk] = __expf(acc[kk] - mx); sum += acc[kk]; }
    const float inv = 1.f / sum;
    float wgt[KWIN];
    #pragma unroll
    for (int kk = 0; kk < KWIN; kk++) wgt[kk] = acc[kk] * inv;

    // ---- V copies finished long ago; barrier is cheap ----
    asm volatile("cp.async.wait_group 0;" ::: "memory");
    __syncthreads();

    // ---- attn @ V from shared (conflict-free lane-consecutive LDS) ----
    float o[HD];
    #pragma unroll
    for (int c = 0; c < HD; c++) o[c] = 0.f;

    const float* vsp = &vs[0][0];
    #pragma unroll
    for (int kk = 0; kk < KWIN; kk++) {
        const float w = wgt[kk];
        const float* vr = vsp + (t + DIL * kk);
        #pragma unroll 8
        for (int c = 0; c < HD; c++)
            o[c] = fmaf(w, vr[c * KV_W], o[c]);
    }

    // ---- store: out[b][0][n][h*32+c] -> one full 128B line per thread ----
    float4* op = (float4*)(out + ((long)b * L + n) * d + h * HD);
    #pragma unroll
    for (int c4 = 0; c4 < HD / 4; c4++)
        op[c4] = make_float4(o[4 * c4 + 0], o[4 * c4 + 1], o[4 * c4 + 2], o[4 * c4 + 3]);
}

extern "C" void kernel_launch(void* const* d_in, const int* in_sizes, int n_in,
                              void* d_out, int out_size)
{
    const float* q = (const float*)d_in[0];
    const float* k = (const float*)d_in[1];
    const float* v = (const float*)d_in[2];
    float* out = (float*)d_out;

    const int grid = 4 * 16 * (4096 / TILE);   // 2048
    dilated_attn_kernel<<<grid, TILE>>>(q, k, v, out);
}

// round 8
// speedup vs baseline: 1.5798x; 1.5798x over previous
#include <cuda_runtime.h>
#include <cuda_bf16.h>

#define TILE  128
#define HALO  12
#define KWIN  9
#define DIL   3
#define HD    32
#define NC2   (HD / 2)          /* 16 channel pairs */
#define KV_W  (TILE + 2*HALO)   /* 152 tokens incl. halo */
#define NP    (KV_W / 2)        /* 76 token-pairs per channel-pair row */
#define NSTG  (NC2 * NP)        /* 1216 staging items per matrix */

typedef unsigned long long u64;

__device__ __forceinline__ u64 pack2(float a, float b) {
    u64 r; asm("mov.b64 %0, {%1, %2};" : "=l"(r) : "f"(a), "f"(b)); return r;
}
__device__ __forceinline__ void unpack2(u64 p, float& a, float& b) {
    asm("mov.b64 {%0, %1}, %2;" : "=f"(a), "=f"(b) : "l"(p));
}
__device__ __forceinline__ u64 fma2(u64 a, u64 b, u64 c) {
    u64 d; asm("fma.rn.f32x2 %0, %1, %2, %3;" : "=l"(d) : "l"(a), "l"(b), "l"(c)); return d;
}

// bounds-checked float2 load of elements n..n+1 (zero-fill OOB = Unfold padding)
__device__ __forceinline__ float2 ld2(const float* __restrict__ row, int n, int L) {
    if (n >= 0 && n + 1 < L) return *(const float2*)(row + n);
    float2 r;
    r.x = ((unsigned)(n + 0) < (unsigned)L) ? row[n + 0] : 0.f;
    r.y = ((unsigned)(n + 1) < (unsigned)L) ? row[n + 1] : 0.f;
    return r;
}

__global__ __launch_bounds__(TILE, 5)
void dilated_attn_kernel(const float* __restrict__ q,
                         const float* __restrict__ k,
                         const float* __restrict__ v,
                         float* __restrict__ out,
                         int B, int d, int L)
{
    // channel-paired layout: ks[c2][nl] = (k[2c2][nl], k[2c2+1][nl]).
    // Staging: vec4 STS at consecutive lane addrs (conflict-free).
    // Compute: LDS.64, lanes stride-2 words -> 256B/warp-op, conflict-free.
    __shared__ float2 ks[NC2][KV_W];
    __shared__ float2 vs[NC2][KV_W];

    const int t    = threadIdx.x;
    const int tile = blockIdx.x & 31;          // L/TILE = 32
    const int h    = (blockIdx.x >> 5) & 15;   // 16 heads
    const int b    = blockIdx.x >> 9;          // 4 batches
    const int n0   = tile * TILE;
    const int n    = n0 + t;

    const long chan_base = ((long)b * d + h * HD) * L;
    const float* kb = k + chan_base;
    const float* vb = v + chan_base;
    const float* qb = q + chan_base;

    // ---- prefetch q (scale folded in); overlaps staging DRAM latency ----
    const float scale = 0.17677669529663687f;   // 32^-0.5
    u64 q2[NC2];
    #pragma unroll
    for (int c2 = 0; c2 < NC2; c2++) {
        const float a  = qb[(long)(2 * c2 + 0) * L + n] * scale;
        const float bq = qb[(long)(2 * c2 + 1) * L + n] * scale;
        q2[c2] = pack2(a, bq);
    }

    // ---- stage K and V together (one barrier total) ----
    #pragma unroll
    for (int it = 0; it < 10; it++) {
        const int idx = t + it * TILE;
        if (idx < NSTG) {
            const int c2 = idx / NP;
            const int np = idx - c2 * NP;
            const int ng = n0 - HALO + np * 2;
            const long r0 = (long)(2 * c2 + 0) * L;
            const long r1 = (long)(2 * c2 + 1) * L;
            const float2 ka = ld2(kb + r0, ng, L);
            const float2 kc = ld2(kb + r1, ng, L);
            const float2 va = ld2(vb + r0, ng, L);
            const float2 vc = ld2(vb + r1, ng, L);
            *(float4*)&ks[c2][np * 2] = make_float4(ka.x, kc.x, ka.y, kc.y);
            *(float4*)&vs[c2][np * 2] = make_float4(va.x, vc.x, va.y, vc.y);
        }
    }
    __syncthreads();

    // ---- QK^T over the 9-wide dilated window (LDS.64 + f32x2 FMA) ----
    u64 acc2[KWIN];
    #pragma unroll
    for (int kk = 0; kk < KWIN; kk++) acc2[kk] = 0ull;

    #pragma unroll
    for (int c2 = 0; c2 < NC2; c2++) {
        const u64 qq = q2[c2];
        const float2* kr = &ks[c2][t];
        #pragma unroll
        for (int kk = 0; kk < KWIN; kk++) {
            const float2 kv2 = kr[DIL * kk];
            acc2[kk] = fma2(qq, pack2(kv2.x, kv2.y), acc2[kk]);
        }
    }

    // ---- softmax over 9 (scale already folded into q) ----
    float s[KWIN];
    float mx = -1e30f;
    #pragma unroll
    for (int kk = 0; kk < KWIN; kk++) {
        float lo, hi; unpack2(acc2[kk], lo, hi);
        s[kk] = lo + hi;
        mx = fmaxf(mx, s[kk]);
    }
    float sum = 0.f;
    #pragma unroll
    for (int kk = 0; kk < KWIN; kk++) { s[kk] = __expf(s[kk] - mx); sum += s[kk]; }
    const float inv = 1.f / sum;
    u64 w2[KWIN];
    #pragma unroll
    for (int kk = 0; kk < KWIN; kk++) { const float w = s[kk] * inv; w2[kk] = pack2(w, w); }

    // ---- attn @ V ----
    u64 o2[NC2];
    #pragma unroll
    for (int c2 = 0; c2 < NC2; c2++) o2[c2] = 0ull;

    #pragma unroll
    for (int kk = 0; kk < KWIN; kk++) {
        const u64 ww = w2[kk];
        const float2* vr = &vs[0][t + DIL * kk];
        #pragma unroll
        for (int c2 = 0; c2 < NC2; c2++) {
            const float2 vv = vr[c2 * KV_W];
            o2[c2] = fma2(ww, pack2(vv.x, vv.y), o2[c2]);
        }
    }

    // ---- store: out[b][0][n][h*32+c] -> one full 128B line per thread ----
    float4* op = (float4*)(out + ((long)b * L + n) * d + h * HD);
    #pragma unroll
    for (int c4 = 0; c4 < HD / 4; c4++) {
        float4 r;
        unpack2(o2[c4 * 2 + 0], r.x, r.y);
        unpack2(o2[c4 * 2 + 1], r.z, r.w);
        op[c4] = r;
    }
}

extern "C" void kernel_launch(void* const* d_in, const int* in_sizes, int n_in,
                              void* d_out, int out_size)
{
    const float* q = (const float*)d_in[0];
    const float* k = (const float*)d_in[1];
    const float* v = (const float*)d_in[2];
    float* out = (float*)d_out;

    const int B = 4, d = 512, L = 4096;
    const int grid = B * (d / HD) * (L / TILE);   // 2048
    dilated_attn_kernel<<<grid, TILE>>>(q, k, v, out, B, d, L);
}

// round 9
// speedup vs baseline: 2.1574x; 1.3656x over previous
#include <cuda_runtime.h>
#include <cuda_fp16.h>

#define TILE  128
#define HALO  12
#define KWIN  9
#define DIL   3
#define HD    32
#define NC2   (HD / 2)          /* 16 channel pairs */
#define KV_W  (TILE + 2*HALO)   /* 152 tokens incl. halo */
#define NQ4   (KV_W / 4)        /* 38 token-quads per channel-pair row */
#define NSTG  (NC2 * NQ4)       /* 608 staging items */

typedef unsigned long long u64;
typedef unsigned int u32;

__device__ __forceinline__ u64 pack2(float a, float b) {
    u64 r; asm("mov.b64 %0, {%1, %2};" : "=l"(r) : "f"(a), "f"(b)); return r;
}
__device__ __forceinline__ void unpack2(u64 p, float& a, float& b) {
    asm("mov.b64 {%0, %1}, %2;" : "=f"(a), "=f"(b) : "l"(p));
}
__device__ __forceinline__ u64 fma2(u64 a, u64 b, u64 c) {
    u64 d; asm("fma.rn.f32x2 %0, %1, %2, %3;" : "=l"(d) : "l"(a), "l"(b), "l"(c)); return d;
}
// half2 -> packed f32x2 (u64)
__device__ __forceinline__ u64 h2f2(__half2 h) {
    const float2 f = __half22float2(h);
    return pack2(f.x, f.y);
}

// bounds-checked float4 load (zero-fill OOB = Unfold padding)
__device__ __forceinline__ float4 ld4(const float* __restrict__ row, int n, int L) {
    if (n >= 0 && n + 3 < L) return *(const float4*)(row + n);
    float4 r;
    r.x = ((unsigned)(n + 0) < (unsigned)L) ? row[n + 0] : 0.f;
    r.y = ((unsigned)(n + 1) < (unsigned)L) ? row[n + 1] : 0.f;
    r.z = ((unsigned)(n + 2) < (unsigned)L) ? row[n + 2] : 0.f;
    r.w = ((unsigned)(n + 3) < (unsigned)L) ? row[n + 3] : 0.f;
    return r;
}

__device__ __forceinline__ u32 h2u(__half2 h) { u32 u; *(__half2*)&u = h; return u; }

__global__ __launch_bounds__(TILE, 7)
void dilated_attn_kernel(const float* __restrict__ q,
                         const float* __restrict__ k,
                         const float* __restrict__ v,
                         float* __restrict__ out,
                         int B, int d, int L)
{
    // half2 channel-pair layout: ks[c2][nl] = (f16 k[2c2][nl], f16 k[2c2+1][nl]).
    // Staging: STS.128 (4 half2) at consecutive lane addrs -> conflict-free.
    // Compute: LDS.32 (one half2), lanes consecutive words -> 1 wavefront/warp-op.
    __shared__ __half2 ks[NC2][KV_W];
    __shared__ __half2 vs[NC2][KV_W];

    const int t    = threadIdx.x;
    const int tile = blockIdx.x & 31;          // L/TILE = 32
    const int h    = (blockIdx.x >> 5) & 15;   // 16 heads
    const int b    = blockIdx.x >> 9;          // 4 batches
    const int n0   = tile * TILE;
    const int n    = n0 + t;

    const long chan_base = ((long)b * d + h * HD) * L;
    const float* kb = k + chan_base;
    const float* vb = v + chan_base;
    const float* qb = q + chan_base;

    // ---- prefetch q as f32 (scale folded in); overlaps staging DRAM latency ----
    const float scale = 0.17677669529663687f;   // 32^-0.5
    u64 q2[NC2];
    #pragma unroll
    for (int c2 = 0; c2 < NC2; c2++) {
        const float a  = qb[(long)(2 * c2 + 0) * L + n] * scale;
        const float bq = qb[(long)(2 * c2 + 1) * L + n] * scale;
        q2[c2] = pack2(a, bq);
    }

    // ---- stage K and V together as f16 (one barrier total) ----
    #pragma unroll
    for (int it = 0; it < 5; it++) {
        const int idx = t + it * TILE;
        if (idx < NSTG) {
            const int c2 = idx / NQ4;
            const int g  = idx - c2 * NQ4;
            const int ng = n0 - HALO + g * 4;
            const long r0 = (long)(2 * c2 + 0) * L;
            const long r1 = (long)(2 * c2 + 1) * L;
            const float4 ka = ld4(kb + r0, ng, L);
            const float4 kc = ld4(kb + r1, ng, L);
            const float4 va = ld4(vb + r0, ng, L);
            const float4 vc = ld4(vb + r1, ng, L);
            uint4 pk, pv;
            pk.x = h2u(__floats2half2_rn(ka.x, kc.x));
            pk.y = h2u(__floats2half2_rn(ka.y, kc.y));
            pk.z = h2u(__floats2half2_rn(ka.z, kc.z));
            pk.w = h2u(__floats2half2_rn(ka.w, kc.w));
            pv.x = h2u(__floats2half2_rn(va.x, vc.x));
            pv.y = h2u(__floats2half2_rn(va.y, vc.y));
            pv.z = h2u(__floats2half2_rn(va.z, vc.z));
            pv.w = h2u(__floats2half2_rn(va.w, vc.w));
            *(uint4*)&ks[c2][g * 4] = pk;
            *(uint4*)&vs[c2][g * 4] = pv;
        }
    }
    __syncthreads();

    // ---- QK^T over the 9-wide dilated window (LDS.32 + cvt + f32x2 FMA) ----
    u64 acc2[KWIN];
    #pragma unroll
    for (int kk = 0; kk < KWIN; kk++) acc2[kk] = 0ull;

    #pragma unroll
    for (int c2 = 0; c2 < NC2; c2++) {
        const u64 qq = q2[c2];
        const __half2* kr = &ks[c2][t];
        #pragma unroll
        for (int kk = 0; kk < KWIN; kk++) {
            acc2[kk] = fma2(qq, h2f2(kr[DIL * kk]), acc2[kk]);
        }
    }

    // ---- softmax over 9 (scale already folded into q) ----
    float s[KWIN];
    float mx = -1e30f;
    #pragma unroll
    for (int kk = 0; kk < KWIN; kk++) {
        float lo, hi; unpack2(acc2[kk], lo, hi);
        s[kk] = lo + hi;
        mx = fmaxf(mx, s[kk]);
    }
    float sum = 0.f;
    #pragma unroll
    for (int kk = 0; kk < KWIN; kk++) { s[kk] = __expf(s[kk] - mx); sum += s[kk]; }
    const float inv = 1.f / sum;
    u64 w2[KWIN];
    #pragma unroll
    for (int kk = 0; kk < KWIN; kk++) { const float w = s[kk] * inv; w2[kk] = pack2(w, w); }

    // ---- attn @ V ----
    u64 o2[NC2];
    #pragma unroll
    for (int c2 = 0; c2 < NC2; c2++) o2[c2] = 0ull;

    #pragma unroll
    for (int kk = 0; kk < KWIN; kk++) {
        const u64 ww = w2[kk];
        const __half2* vr = &vs[0][t + DIL * kk];
        #pragma unroll
        for (int c2 = 0; c2 < NC2; c2++) {
            o2[c2] = fma2(ww, h2f2(vr[c2 * KV_W]), o2[c2]);
        }
    }

    // ---- store: out[b][0][n][h*32+c] -> one full 128B line per thread ----
    float4* op = (float4*)(out + ((long)b * L + n) * d + h * HD);
    #pragma unroll
    for (int c4 = 0; c4 < HD / 4; c4++) {
        float4 r;
        unpack2(o2[c4 * 2 + 0], r.x, r.y);
        unpack2(o2[c4 * 2 + 1], r.z, r.w);
        op[c4] = r;
    }
}

extern "C" void kernel_launch(void* const* d_in, const int* in_sizes, int n_in,
                              void* d_out, int out_size)
{
    const float* q = (const float*)d_in[0];
    const float* k = (const float*)d_in[1];
    const float* v = (const float*)d_in[2];
    float* out = (float*)d_out;

    const int B = 4, d = 512, L = 4096;
    const int grid = B * (d / HD) * (L / TILE);   // 2048
    dilated_attn_kernel<<<grid, TILE>>>(q, k, v, out, B, d, L);
}